// round 2
// baseline (speedup 1.0000x reference)
#include <cuda_runtime.h>
#include <math.h>

typedef unsigned long long ull;

#define VOCAB 10000
#define H 1024
#define H2 2048
#define BB 32
#define TT 128
#define MROWS (BB*TT)   // 4096
#define NB 128          // persistent grid CTAs
#define NTHR 256

// ---------------- scratch (device globals; no allocations allowed) ----------
__device__ __align__(16) float g_x[MROWS * H];          // embedded inputs
__device__ __align__(16) float g_gx0[TT * H2 * BB];     // [t][n][m] x@Wg0x
__device__ __align__(16) float g_cx0[TT * H * BB];      // [t][n][m] x@Wc0x
__device__ __align__(16) float g_outT[TT * H * BB];     // [t][n][m] h1 sequence
__device__ __align__(16) float g_out2[MROWS * H];       // [m*T+t][n]
__device__ __align__(16) float g_h0T[H * BB];
__device__ __align__(16) float g_h1T[H * BB];
__device__ __align__(16) float g_rhT[H * BB];
__device__ __align__(16) float g_uT[H * BB];
__device__ __align__(16) float g_Tg0[H * H2];           // interleaved [k/4][n][4]
__device__ __align__(16) float g_Tc0[H * H];
__device__ __align__(16) float g_Tg1[H2 * H2];
__device__ __align__(16) float g_Tc1[H2 * H];
__device__ volatile unsigned g_cnt;
__device__ volatile unsigned g_gen;

// ---------------- f32x2 packed helpers --------------------------------------
__device__ __forceinline__ ull pdup(float x) {
    ull r; asm("mov.b64 %0, {%1, %1};" : "=l"(r) : "f"(x)); return r;
}
__device__ __forceinline__ ull f2fma(ull acc, ull a, ull b) {
    ull d; asm("fma.rn.f32x2 %0, %1, %2, %3;" : "=l"(d) : "l"(a), "l"(b), "l"(acc));
    return d;
}
__device__ __forceinline__ ull f2add(ull a, ull b) {
    ull d; asm("add.rn.f32x2 %0, %1, %2;" : "=l"(d) : "l"(a), "l"(b)); return d;
}
__device__ __forceinline__ float plo(ull v) { return __uint_as_float((unsigned)v); }
__device__ __forceinline__ float phi(ull v) { return __uint_as_float((unsigned)(v >> 32)); }

__device__ __forceinline__ float sigf(float x) {
    return __fdividef(1.f, 1.f + __expf(-x));
}
__device__ __forceinline__ float tanhx(float x) {
    // tanh(x) = 1 - 2/(e^{2x}+1); exact limits at +-inf with __expf/__fdividef
    return 1.f - __fdividef(2.f, __expf(2.f * x) + 1.f);
}

// ---------------- small utility kernels --------------------------------------
__global__ void embed_k(const int* __restrict__ idx, const float* __restrict__ emb,
                        float* __restrict__ x) {
    int row = blockIdx.x;
    int tid = threadIdx.x;
    const float4* src = (const float4*)(emb + (size_t)idx[row] * H);
    float4* dst = (float4*)(x + (size_t)row * H);
    dst[tid] = src[tid];
}

// W[srow0+k][n] (row-major, leading dim ld) -> dst[((k/4)*N + n)*4 + (k%4)]
__global__ void prep_w(const float* __restrict__ src, int srow0, int ld,
                       int K, int N, float* __restrict__ dst) {
    int idx = blockIdx.x * 256 + threadIdx.x;
    if (idx >= K * N) return;
    int k = idx / N;
    int n = idx - k * N;
    dst[((size_t)(k >> 2) * N + n) * 4 + (k & 3)] = src[(size_t)(srow0 + k) * ld + n];
}

// outT[t][n][m] -> out[(m*T+t)*H + n]
__global__ void transp_out(const float* __restrict__ outT, float* __restrict__ out) {
    __shared__ float s[32][33];
    int t = blockIdx.x;
    int nb = blockIdx.y * 32;
    int tx = threadIdx.x, ty = threadIdx.y;   // (32, 8)
#pragma unroll
    for (int i = 0; i < 32; i += 8)
        s[ty + i][tx] = outT[((size_t)t * H + nb + ty + i) * BB + tx];
    __syncthreads();
#pragma unroll
    for (int i = 0; i < 32; i += 8)
        out[((size_t)(ty + i) * TT + t) * H + nb + tx] = s[tx][ty + i];
}

// ---------------- big GEMM (f32x2): C[M,N] = A[M,K] @ B (+bias) -------------
// BT=false: B row-major [K,N]. BT=true: B row-major [N,K] (ldb=K).
// GRUL=true: write C[((row%T)*N + n)*32 + row/T] instead of C[row*N+n].
template<bool BT, bool GRUL>
__global__ void gemm_big(const float* __restrict__ A, const float* __restrict__ Bm,
                         const float* __restrict__ bias, float* __restrict__ C,
                         int M, int N, int K, int ldb)
{
    __shared__ __align__(16) float As[16][132];
    __shared__ __align__(16) float Bs[16][68];

    int m0 = blockIdx.y * 128;
    int n0 = blockIdx.x * 64;
    int tid = threadIdx.x;
    int rowg = tid >> 4;
    int colg = tid & 15;
    int mm0 = rowg * 8;
    int nn0 = colg * 4;

    ull acc2[4][4];
#pragma unroll
    for (int p = 0; p < 4; p++)
#pragma unroll
        for (int c = 0; c < 4; c++) acc2[p][c] = 0ull;

    for (int k0 = 0; k0 < K; k0 += 16) {
#pragma unroll
        for (int i = 0; i < 2; i++) {
            int f  = tid + i * 256;
            int am = f >> 2;
            int kq = f & 3;
            float4 v = *(const float4*)(A + (size_t)(m0 + am) * K + k0 + kq * 4);
            As[kq * 4 + 0][am] = v.x;
            As[kq * 4 + 1][am] = v.y;
            As[kq * 4 + 2][am] = v.z;
            As[kq * 4 + 3][am] = v.w;
        }
        if (!BT) {
            int brow = tid >> 4;
            int colq = tid & 15;
            int n = n0 + colq * 4;
            float4 v;
            if (n + 3 < N) {
                v = *(const float4*)(Bm + (size_t)(k0 + brow) * ldb + n);
            } else {
                v.x = (n + 0 < N) ? Bm[(size_t)(k0 + brow) * ldb + n + 0] : 0.f;
                v.y = (n + 1 < N) ? Bm[(size_t)(k0 + brow) * ldb + n + 1] : 0.f;
                v.z = (n + 2 < N) ? Bm[(size_t)(k0 + brow) * ldb + n + 2] : 0.f;
                v.w = (n + 3 < N) ? Bm[(size_t)(k0 + brow) * ldb + n + 3] : 0.f;
            }
            *(float4*)&Bs[brow][colq * 4] = v;
        } else {
            int nrow = tid >> 2;
            int kq = tid & 3;
            int n = n0 + nrow;
            float4 v = make_float4(0.f, 0.f, 0.f, 0.f);
            if (n < N) v = *(const float4*)(Bm + (size_t)n * ldb + k0 + kq * 4);
            Bs[kq * 4 + 0][nrow] = v.x;
            Bs[kq * 4 + 1][nrow] = v.y;
            Bs[kq * 4 + 2][nrow] = v.z;
            Bs[kq * 4 + 3][nrow] = v.w;
        }
        __syncthreads();
#pragma unroll
        for (int kk = 0; kk < 16; kk++) {
            ulonglong2 a01 = *(const ulonglong2*)&As[kk][mm0];
            ulonglong2 a23 = *(const ulonglong2*)&As[kk][mm0 + 4];
            float4 tb = *(const float4*)&Bs[kk][nn0];
            ull b0 = pdup(tb.x), b1 = pdup(tb.y), b2 = pdup(tb.z), b3 = pdup(tb.w);
            acc2[0][0] = f2fma(acc2[0][0], a01.x, b0);
            acc2[0][1] = f2fma(acc2[0][1], a01.x, b1);
            acc2[0][2] = f2fma(acc2[0][2], a01.x, b2);
            acc2[0][3] = f2fma(acc2[0][3], a01.x, b3);
            acc2[1][0] = f2fma(acc2[1][0], a01.y, b0);
            acc2[1][1] = f2fma(acc2[1][1], a01.y, b1);
            acc2[1][2] = f2fma(acc2[1][2], a01.y, b2);
            acc2[1][3] = f2fma(acc2[1][3], a01.y, b3);
            acc2[2][0] = f2fma(acc2[2][0], a23.x, b0);
            acc2[2][1] = f2fma(acc2[2][1], a23.x, b1);
            acc2[2][2] = f2fma(acc2[2][2], a23.x, b2);
            acc2[2][3] = f2fma(acc2[2][3], a23.x, b3);
            acc2[3][0] = f2fma(acc2[3][0], a23.y, b0);
            acc2[3][1] = f2fma(acc2[3][1], a23.y, b1);
            acc2[3][2] = f2fma(acc2[3][2], a23.y, b2);
            acc2[3][3] = f2fma(acc2[3][3], a23.y, b3);
        }
        __syncthreads();
    }

#pragma unroll
    for (int p = 0; p < 4; p++) {
#pragma unroll
        for (int c = 0; c < 4; c++) {
            int n = n0 + nn0 + c;
            if (n < N) {
                float v0 = plo(acc2[p][c]);
                float v1 = phi(acc2[p][c]);
                if (bias) { v0 += bias[n]; v1 += bias[n]; }
                int r0 = m0 + mm0 + 2 * p;
                int r1 = r0 + 1;
                if (GRUL) {
                    C[((size_t)(r0 & (TT - 1)) * N + n) * BB + (r0 >> 7)] = v0;
                    C[((size_t)(r1 & (TT - 1)) * N + n) * BB + (r1 >> 7)] = v1;
                } else {
                    C[(size_t)r0 * N + n] = v0;
                    C[(size_t)r1 * N + n] = v1;
                }
            }
        }
    }
}

// ---------------- persistent recurrence kernel --------------------------------
__device__ __forceinline__ void gsync() {
    __syncthreads();
    if (threadIdx.x == 0) {
        unsigned gen = g_gen;
        __threadfence();
        unsigned old = atomicAdd((unsigned*)&g_cnt, 1u);
        if (old == NB - 1) {
            g_cnt = 0;
            __threadfence();
            g_gen = gen + 1;
        } else {
            while (g_gen == gen) __nanosleep(32);
            __threadfence();
        }
    }
    __syncthreads();
}

__device__ __forceinline__ void load_tile(float* __restrict__ As,
                                          const float* __restrict__ AT,
                                          int k0, int tid) {
    const float4* src = (const float4*)(AT + (size_t)k0 * BB);
    float4* dst = (float4*)As;
#pragma unroll
    for (int i = 0; i < 8; i++) dst[i * NTHR + tid] = src[i * NTHR + tid];
}

// packed pair over m: acc(f32x2) += sum_k A[k][m0:m0+2] * W[n][k]
__device__ __forceinline__ ull acc_pack2(ull acc, const float* __restrict__ AT,
                                         const float* __restrict__ W4, int n, int N,
                                         int K, int kabs0, float* __restrict__ As,
                                         int tid, int m0) {
    for (int k0 = 0; k0 < K; k0 += 256) {
        __syncthreads();
        load_tile(As, AT, k0, tid);
        __syncthreads();
        const float4* Wp = (const float4*)W4 + (size_t)((kabs0 + k0) >> 2) * N + n;
#pragma unroll 8
        for (int kk = 0; kk < 256; kk += 4) {
            float4 w = *Wp; Wp += N;
            ull w0 = pdup(w.x), w1 = pdup(w.y), w2 = pdup(w.z), w3 = pdup(w.w);
            acc = f2fma(acc, *(const ull*)(As + (kk + 0) * BB + m0), w0);
            acc = f2fma(acc, *(const ull*)(As + (kk + 1) * BB + m0), w1);
            acc = f2fma(acc, *(const ull*)(As + (kk + 2) * BB + m0), w2);
            acc = f2fma(acc, *(const ull*)(As + (kk + 3) * BB + m0), w3);
        }
    }
    return acc;
}

__device__ __forceinline__ float acc_scalar(float acc, const float* __restrict__ AT,
                                            const float* __restrict__ W4, int n, int N,
                                            int K, int kabs0, float* __restrict__ As,
                                            int tid, int m) {
    for (int k0 = 0; k0 < K; k0 += 256) {
        __syncthreads();
        load_tile(As, AT, k0, tid);
        __syncthreads();
        const float4* Wp = (const float4*)W4 + (size_t)((kabs0 + k0) >> 2) * N + n;
#pragma unroll 8
        for (int kk = 0; kk < 256; kk += 4) {
            float4 w = *Wp; Wp += N;
            acc = fmaf(As[(kk + 0) * BB + m], w.x, acc);
            acc = fmaf(As[(kk + 1) * BB + m], w.y, acc);
            acc = fmaf(As[(kk + 2) * BB + m], w.z, acc);
            acc = fmaf(As[(kk + 3) * BB + m], w.w, acc);
        }
    }
    return acc;
}

__global__ void __launch_bounds__(NTHR, 1)
rnn_persist(const float* __restrict__ bg0, const float* __restrict__ bc0,
            const float* __restrict__ bg1, const float* __restrict__ bc1)
{
    __shared__ __align__(16) float As[256 * BB];   // 32 KB
    int tid = threadIdx.x;
    int gt = blockIdx.x * NTHR + tid;              // 0..32767

    // init states
    g_h0T[gt] = 0.f;
    g_h1T[gt] = 0.f;
    gsync();

    int nG = gt >> 4;            // 0..2047
    int mG = (gt & 15) * 2;      // 0,2,..,30
    int nC = gt >> 5;            // 0..1023
    int mC = gt & 31;

    for (int t = 0; t < TT; t++) {
        // ---- layer 0 gates: sigmoid(h0@Wg0h + x-pre + bg0)
        {
            ull acc = acc_pack2(0ull, g_h0T, g_Tg0, nG, H2, H, 0, As, tid, mG);
            ull pre = *(const ull*)(g_gx0 + ((size_t)t * H2 + nG) * BB + mG);
            acc = f2add(acc, pre);
            float b = bg0[nG];
            float v0 = sigf(plo(acc) + b);
            float v1 = sigf(phi(acc) + b);
            if (nG < H) {
                g_rhT[nG * BB + mG]     = v0 * g_h0T[nG * BB + mG];
                g_rhT[nG * BB + mG + 1] = v1 * g_h0T[nG * BB + mG + 1];
            } else {
                g_uT[(nG - H) * BB + mG]     = v0;
                g_uT[(nG - H) * BB + mG + 1] = v1;
            }
        }
        gsync();
        // ---- layer 0 candidate + state update
        {
            float a = acc_scalar(0.f, g_rhT, g_Tc0, nC, H, H, 0, As, tid, mC);
            a += bc0[nC] + g_cx0[((size_t)t * H + nC) * BB + mC];
            float c = tanhx(a);
            float u = g_uT[nC * BB + mC];
            float h = g_h0T[nC * BB + mC];
            g_h0T[nC * BB + mC] = u * h + (1.f - u) * c;
        }
        gsync();
        // ---- layer 1 gates (K = 2048: [h0; h1])
        {
            ull acc = acc_pack2(0ull, g_h0T, g_Tg1, nG, H2, H, 0, As, tid, mG);
            acc = acc_pack2(acc, g_h1T, g_Tg1, nG, H2, H, H, As, tid, mG);
            float b = bg1[nG];
            float v0 = sigf(plo(acc) + b);
            float v1 = sigf(phi(acc) + b);
            if (nG < H) {
                g_rhT[nG * BB + mG]     = v0 * g_h1T[nG * BB + mG];
                g_rhT[nG * BB + mG + 1] = v1 * g_h1T[nG * BB + mG + 1];
            } else {
                g_uT[(nG - H) * BB + mG]     = v0;
                g_uT[(nG - H) * BB + mG + 1] = v1;
            }
        }
        gsync();
        // ---- layer 1 candidate + state update + output
        {
            float a = acc_scalar(0.f, g_h0T, g_Tc1, nC, H, H, 0, As, tid, mC);
            a = acc_scalar(a, g_rhT, g_Tc1, nC, H, H, H, As, tid, mC);
            a += bc1[nC];
            float c = tanhx(a);
            float u = g_uT[nC * BB + mC];
            float h = g_h1T[nC * BB + mC];
            float hn = u * h + (1.f - u) * c;
            g_h1T[nC * BB + mC] = hn;
            g_outT[((size_t)t * H + nC) * BB + mC] = hn;
        }
        gsync();
    }
}

// ---------------- launch ------------------------------------------------------
extern "C" void kernel_launch(void* const* d_in, const int* in_sizes, int n_in,
                              void* d_out, int out_size)
{
    const int*   idx = (const int*)  d_in[0];
    const float* emb = (const float*)d_in[1];
    const float* Wg0 = (const float*)d_in[2];
    const float* bg0 = (const float*)d_in[3];
    const float* Wc0 = (const float*)d_in[4];
    const float* bc0 = (const float*)d_in[5];
    const float* Wg1 = (const float*)d_in[6];
    const float* bg1 = (const float*)d_in[7];
    const float* Wc1 = (const float*)d_in[8];
    const float* bc1 = (const float*)d_in[9];
    const float* smb = (const float*)d_in[10];
    float* out = (float*)d_out;

    float *px, *pgx0, *pcx0, *poutT, *pout2, *pTg0, *pTc0, *pTg1, *pTc1;
    cudaGetSymbolAddress((void**)&px,    g_x);
    cudaGetSymbolAddress((void**)&pgx0,  g_gx0);
    cudaGetSymbolAddress((void**)&pcx0,  g_cx0);
    cudaGetSymbolAddress((void**)&poutT, g_outT);
    cudaGetSymbolAddress((void**)&pout2, g_out2);
    cudaGetSymbolAddress((void**)&pTg0,  g_Tg0);
    cudaGetSymbolAddress((void**)&pTc0,  g_Tc0);
    cudaGetSymbolAddress((void**)&pTg1,  g_Tg1);
    cudaGetSymbolAddress((void**)&pTc1,  g_Tc1);

    // weight prep: transpose + k-quad interleave (h-parts for layer 0)
    prep_w<<<(H * H2) / 256, 256>>>(Wg0, 1024, H2, H, H2, pTg0);
    prep_w<<<(H * H) / 256, 256>>>(Wc0, 1024, H, H, H, pTc0);
    prep_w<<<(H2 * H2) / 256, 256>>>(Wg1, 0, H2, H2, H2, pTg1);
    prep_w<<<(H2 * H) / 256, 256>>>(Wc1, 0, H, H2, H, pTc1);

    // embed
    embed_k<<<MROWS, 256>>>(idx, emb, px);

    // precompute layer-0 x-projections into [t][n][m] layout
    gemm_big<false, true><<<dim3(H2 / 64, MROWS / 128), 256>>>(px, Wg0, nullptr, pgx0,
                                                               MROWS, H2, H, H2);
    gemm_big<false, true><<<dim3(H / 64, MROWS / 128), 256>>>(px, Wc0, nullptr, pcx0,
                                                              MROWS, H, H, H);

    // the full 128-step recurrence in one persistent kernel
    rnn_persist<<<NB, NTHR>>>(bg0, bc0, bg1, bc1);

    // reorder h1 sequence to [m*T+t][n] for the logits GEMM
    transp_out<<<dim3(TT, H / 32), dim3(32, 8)>>>(poutT, pout2);

    // tied-softmax logits: [4096,1024] @ emb[10000,1024]^T + bias
    gemm_big<true, false><<<dim3((VOCAB + 63) / 64, MROWS / 128), 256>>>(pout2, emb, smb,
                                                                         out, MROWS, VOCAB,
                                                                         H, H);
}

// round 3
// speedup vs baseline: 1.4413x; 1.4413x over previous
#include <cuda_runtime.h>
#include <math.h>

typedef unsigned long long ull;

#define VOCAB 10000
#define H 1024
#define H2 2048
#define BB 32
#define TT 128
#define MROWS (BB*TT)   // 4096
#define NB 128          // persistent grid CTAs
#define NTHR 256

// smem layout (floats), dynamic: total 24576 floats = 96KB
#define SM_A0_0 0
#define SM_A0_1 4096
#define SM_A1_0 8192
#define SM_A1_1 12288
#define SM_W0_0 16384
#define SM_W0_1 18432
#define SM_W1_0 20480
#define SM_W1_1 22528
#define SM_FLOATS 24576

// ---------------- scratch (device globals; no allocations allowed) ----------
__device__ __align__(16) float g_x[MROWS * H];
__device__ __align__(16) float g_gx0[TT * H2 * BB];     // [t][n][m]
__device__ __align__(16) float g_cx0[TT * H * BB];      // [t][n][m]
__device__ __align__(16) float g_outT[TT * H * BB];     // [t][n][m]
__device__ __align__(16) float g_out2[MROWS * H];       // [m*T+t][n]
__device__ __align__(16) float g_h0T[2][H * BB];        // ping-pong
__device__ __align__(16) float g_h1T[H * BB];
__device__ __align__(16) float g_rh0[H * BB];
__device__ __align__(16) float g_u0[H * BB];
__device__ __align__(16) float g_rh1[H * BB];
__device__ __align__(16) float g_u1[H * BB];
__device__ __align__(16) float g_Tg0[H * H2];           // [(k/4)*N + n][4]
__device__ __align__(16) float g_Tc0[H * H];
__device__ __align__(16) float g_Tg1[H2 * H2];
__device__ __align__(16) float g_Tc1[H2 * H];
__device__ volatile unsigned g_cnt;
__device__ volatile unsigned g_gen;

// ---------------- f32x2 packed helpers --------------------------------------
__device__ __forceinline__ ull pdup(float x) {
    ull r; asm("mov.b64 %0, {%1, %1};" : "=l"(r) : "f"(x)); return r;
}
__device__ __forceinline__ ull f2fma(ull acc, ull a, ull b) {
    ull d; asm("fma.rn.f32x2 %0, %1, %2, %3;" : "=l"(d) : "l"(a), "l"(b), "l"(acc));
    return d;
}
__device__ __forceinline__ ull f2add(ull a, ull b) {
    ull d; asm("add.rn.f32x2 %0, %1, %2;" : "=l"(d) : "l"(a), "l"(b)); return d;
}
__device__ __forceinline__ float plo(ull v) { return __uint_as_float((unsigned)v); }
__device__ __forceinline__ float phi(ull v) { return __uint_as_float((unsigned)(v >> 32)); }

__device__ __forceinline__ float sigf(float x) {
    return __fdividef(1.f, 1.f + __expf(-x));
}
__device__ __forceinline__ float tanhx(float x) {
    return 1.f - __fdividef(2.f, __expf(2.f * x) + 1.f);
}

// ---------------- cp.async ----------------------------------------------------
__device__ __forceinline__ void cp16(float* d, const float* s) {
    unsigned ds = (unsigned)__cvta_generic_to_shared(d);
    asm volatile("cp.async.cg.shared.global [%0], [%1], 16;" :: "r"(ds), "l"(s) : "memory");
}
#define CP_COMMIT asm volatile("cp.async.commit_group;" ::: "memory")
#define CP_WAIT1  asm volatile("cp.async.wait_group 1;" ::: "memory")
#define CP_WAIT0  asm volatile("cp.async.wait_group 0;" ::: "memory")

// ---------------- grid barrier ------------------------------------------------
__device__ __forceinline__ void gsync() {
    __threadfence();
    __syncthreads();
    if (threadIdx.x == 0) {
        unsigned gen = g_gen;
        unsigned old = atomicAdd((unsigned*)&g_cnt, 1u);
        if (old == NB - 1) {
            g_cnt = 0;
            __threadfence();
            g_gen = gen + 1;
        } else {
            while (g_gen == gen) { }
        }
    }
    __syncthreads();
}

// ---------------- small utility kernels --------------------------------------
__global__ void embed_k(const int* __restrict__ idx, const float* __restrict__ emb,
                        float* __restrict__ x) {
    int row = blockIdx.x;
    int tid = threadIdx.x;
    const float4* src = (const float4*)(emb + (size_t)idx[row] * H);
    float4* dst = (float4*)(x + (size_t)row * H);
    dst[tid] = src[tid];
}

__global__ void prep_w(const float* __restrict__ src, int srow0, int ld,
                       int K, int N, float* __restrict__ dst) {
    int idx = blockIdx.x * 256 + threadIdx.x;
    if (idx >= K * N) return;
    int k = idx / N;
    int n = idx - k * N;
    dst[((size_t)(k >> 2) * N + n) * 4 + (k & 3)] = src[(size_t)(srow0 + k) * ld + n];
}

__global__ void transp_out(const float* __restrict__ outT, float* __restrict__ out) {
    __shared__ float s[32][33];
    int t = blockIdx.x;
    int nb = blockIdx.y * 32;
    int tx = threadIdx.x, ty = threadIdx.y;
#pragma unroll
    for (int i = 0; i < 32; i += 8)
        s[ty + i][tx] = outT[((size_t)t * H + nb + ty + i) * BB + tx];
    __syncthreads();
#pragma unroll
    for (int i = 0; i < 32; i += 8)
        out[((size_t)(ty + i) * TT + t) * H + nb + tx] = s[tx][ty + i];
}

// ---------------- big GEMM (f32x2) -------------------------------------------
template<bool BT, bool GRUL>
__global__ void gemm_big(const float* __restrict__ A, const float* __restrict__ Bm,
                         const float* __restrict__ bias, float* __restrict__ C,
                         int M, int N, int K, int ldb)
{
    __shared__ __align__(16) float As[16][132];
    __shared__ __align__(16) float Bs[16][68];

    int m0 = blockIdx.y * 128;
    int n0 = blockIdx.x * 64;
    int tid = threadIdx.x;
    int rowg = tid >> 4;
    int colg = tid & 15;
    int mm0 = rowg * 8;
    int nn0 = colg * 4;

    ull acc2[4][4];
#pragma unroll
    for (int p = 0; p < 4; p++)
#pragma unroll
        for (int c = 0; c < 4; c++) acc2[p][c] = 0ull;

    for (int k0 = 0; k0 < K; k0 += 16) {
#pragma unroll
        for (int i = 0; i < 2; i++) {
            int f  = tid + i * 256;
            int am = f >> 2;
            int kq = f & 3;
            float4 v = *(const float4*)(A + (size_t)(m0 + am) * K + k0 + kq * 4);
            As[kq * 4 + 0][am] = v.x;
            As[kq * 4 + 1][am] = v.y;
            As[kq * 4 + 2][am] = v.z;
            As[kq * 4 + 3][am] = v.w;
        }
        if (!BT) {
            int brow = tid >> 4;
            int colq = tid & 15;
            int n = n0 + colq * 4;
            float4 v;
            if (n + 3 < N) {
                v = *(const float4*)(Bm + (size_t)(k0 + brow) * ldb + n);
            } else {
                v.x = (n + 0 < N) ? Bm[(size_t)(k0 + brow) * ldb + n + 0] : 0.f;
                v.y = (n + 1 < N) ? Bm[(size_t)(k0 + brow) * ldb + n + 1] : 0.f;
                v.z = (n + 2 < N) ? Bm[(size_t)(k0 + brow) * ldb + n + 2] : 0.f;
                v.w = (n + 3 < N) ? Bm[(size_t)(k0 + brow) * ldb + n + 3] : 0.f;
            }
            *(float4*)&Bs[brow][colq * 4] = v;
        } else {
            int nrow = tid >> 2;
            int kq = tid & 3;
            int n = n0 + nrow;
            float4 v = make_float4(0.f, 0.f, 0.f, 0.f);
            if (n < N) v = *(const float4*)(Bm + (size_t)n * ldb + k0 + kq * 4);
            Bs[kq * 4 + 0][nrow] = v.x;
            Bs[kq * 4 + 1][nrow] = v.y;
            Bs[kq * 4 + 2][nrow] = v.z;
            Bs[kq * 4 + 3][nrow] = v.w;
        }
        __syncthreads();
#pragma unroll
        for (int kk = 0; kk < 16; kk++) {
            ulonglong2 a01 = *(const ulonglong2*)&As[kk][mm0];
            ulonglong2 a23 = *(const ulonglong2*)&As[kk][mm0 + 4];
            float4 tb = *(const float4*)&Bs[kk][nn0];
            ull b0 = pdup(tb.x), b1 = pdup(tb.y), b2 = pdup(tb.z), b3 = pdup(tb.w);
            acc2[0][0] = f2fma(acc2[0][0], a01.x, b0);
            acc2[0][1] = f2fma(acc2[0][1], a01.x, b1);
            acc2[0][2] = f2fma(acc2[0][2], a01.x, b2);
            acc2[0][3] = f2fma(acc2[0][3], a01.x, b3);
            acc2[1][0] = f2fma(acc2[1][0], a01.y, b0);
            acc2[1][1] = f2fma(acc2[1][1], a01.y, b1);
            acc2[1][2] = f2fma(acc2[1][2], a01.y, b2);
            acc2[1][3] = f2fma(acc2[1][3], a01.y, b3);
            acc2[2][0] = f2fma(acc2[2][0], a23.x, b0);
            acc2[2][1] = f2fma(acc2[2][1], a23.x, b1);
            acc2[2][2] = f2fma(acc2[2][2], a23.x, b2);
            acc2[2][3] = f2fma(acc2[2][3], a23.x, b3);
            acc2[3][0] = f2fma(acc2[3][0], a23.y, b0);
            acc2[3][1] = f2fma(acc2[3][1], a23.y, b1);
            acc2[3][2] = f2fma(acc2[3][2], a23.y, b2);
            acc2[3][3] = f2fma(acc2[3][3], a23.y, b3);
        }
        __syncthreads();
    }

#pragma unroll
    for (int p = 0; p < 4; p++) {
#pragma unroll
        for (int c = 0; c < 4; c++) {
            int n = n0 + nn0 + c;
            if (n < N) {
                float v0 = plo(acc2[p][c]);
                float v1 = phi(acc2[p][c]);
                if (bias) { v0 += bias[n]; v1 += bias[n]; }
                int r0 = m0 + mm0 + 2 * p;
                int r1 = r0 + 1;
                if (GRUL) {
                    C[((size_t)(r0 & (TT - 1)) * N + n) * BB + (r0 >> 7)] = v0;
                    C[((size_t)(r1 & (TT - 1)) * N + n) * BB + (r1 >> 7)] = v1;
                } else {
                    C[(size_t)r0 * N + n] = v0;
                    C[(size_t)r1 * N + n] = v1;
                }
            }
        }
    }
}

// ---------------- recurrence MAC cores ----------------------------------------
// gates: one n-column, 4 batch rows (m0..m0+3), per q: 1 LDS.128 W + 4 LDS.128 A
// + 8 f2fma. Wb slice has 16 n columns.
__device__ __forceinline__ void mac_quad(ull& p01a, ull& p01b, ull& p23a, ull& p23b,
                                         const float* __restrict__ Ab,
                                         const float* __restrict__ Wb,
                                         int nl, int m0)
{
    const float4* wp = (const float4*)Wb + nl;
#pragma unroll 8
    for (int q = 0; q < 32; q++) {
        float4 w = wp[q * 16];
        const float* ak = Ab + q * 128 + m0;
        ulonglong2 a0 = *(const ulonglong2*)(ak);
        ulonglong2 a1 = *(const ulonglong2*)(ak + 32);
        ulonglong2 a2 = *(const ulonglong2*)(ak + 64);
        ulonglong2 a3 = *(const ulonglong2*)(ak + 96);
        ull w0 = pdup(w.x), w1 = pdup(w.y), w2 = pdup(w.z), w3 = pdup(w.w);
        p01a = f2fma(p01a, a0.x, w0); p23a = f2fma(p23a, a0.y, w0);
        p01b = f2fma(p01b, a1.x, w1); p23b = f2fma(p23b, a1.y, w1);
        p01a = f2fma(p01a, a2.x, w2); p23a = f2fma(p23a, a2.y, w2);
        p01b = f2fma(p01b, a3.x, w3); p23b = f2fma(p23b, a3.y, w3);
    }
}

// cand: one n-column, 2 batch rows. Wb slice has 8 n columns.
__device__ __forceinline__ void mac_pair(ull& pa, ull& pb,
                                         const float* __restrict__ Ab,
                                         const float* __restrict__ Wb,
                                         int nl, int m0)
{
    const float4* wp = (const float4*)Wb + nl;
#pragma unroll 8
    for (int q = 0; q < 32; q++) {
        float4 w = wp[q * 8];
        const float* ak = Ab + q * 128 + m0;
        ull a0 = *(const ull*)(ak);
        ull a1 = *(const ull*)(ak + 32);
        ull a2 = *(const ull*)(ak + 64);
        ull a3 = *(const ull*)(ak + 96);
        pa = f2fma(pa, a0, pdup(w.x));
        pb = f2fma(pb, a1, pdup(w.y));
        pa = f2fma(pa, a2, pdup(w.z));
        pb = f2fma(pb, a3, pdup(w.w));
    }
}

// ---------------- persistent pipelined recurrence -----------------------------
__global__ void __launch_bounds__(NTHR, 1)
rnn_persist(const float* __restrict__ bg0, const float* __restrict__ bc0,
            const float* __restrict__ bg1, const float* __restrict__ bc1)
{
    extern __shared__ __align__(16) float sm[];
    const int tid = threadIdx.x;
    const int c   = blockIdx.x;
    const int gt  = c * NTHR + tid;

    // zero initial states
    g_h0T[0][gt] = 0.f;
    g_h1T[gt] = 0.f;
    g_h0T[0][gt + NB * NTHR] = 0.f;     // cover full 32768? H*BB = 32768 = NB*NTHR
    // (H*BB == NB*NTHR == 32768, so first two lines cover everything; third is a
    //  duplicate guard only if sizes changed — remove effect by clamping)
    gsync();

    const int side = tid >> 7;          // 0: layer0 work, 1: layer1 work
    const int idx  = tid & 127;
    // gates mapping
    const int gnl = idx >> 3, gm0 = (idx & 7) * 4;
    const int gn  = c * 16 + gnl;
    // cand mapping
    const int cnl = idx >> 4, cm0 = (idx & 15) * 2;
    const int cn  = c * 8 + cnl;

    int cur = 0;

    for (int t = 0; t <= TT; t++) {
        const bool do0 = (t < TT);
        const bool do1 = (t > 0);
        const float* __restrict__ h0c = g_h0T[cur];
        const int nc = do1 ? 16 : 8;

        // ============== PHASE A: gates ==============
        {
            // ---- stage chunk kc into buffer b
            auto stageA = [&](int kc) {
                float* A0 = sm + ((kc & 1) ? SM_A0_1 : SM_A0_0);
                const float* hs = (kc < 8) ? (h0c + kc * 4096)
                                           : (g_h1T + (kc - 8) * 4096);
                #pragma unroll
                for (int u = 0; u < 4; u++)
                    cp16(A0 + (tid + u * NTHR) * 4, hs + (tid + u * NTHR) * 4);
                if (do0 && kc < 8) {
                    float* W0 = sm + ((kc & 1) ? SM_W0_1 : SM_W0_0);
                    #pragma unroll
                    for (int u = 0; u < 2; u++) {
                        int e = tid + u * NTHR;
                        int q = e >> 4, nl2 = e & 15;
                        cp16(W0 + e * 4,
                             g_Tg0 + ((size_t)(kc * 32 + q) * H2 + c * 16 + nl2) * 4);
                    }
                }
                if (do1) {
                    float* W1 = sm + ((kc & 1) ? SM_W1_1 : SM_W1_0);
                    #pragma unroll
                    for (int u = 0; u < 2; u++) {
                        int e = tid + u * NTHR;
                        int q = e >> 4, nl2 = e & 15;
                        cp16(W1 + e * 4,
                             g_Tg1 + ((size_t)(kc * 32 + q) * H2 + c * 16 + nl2) * 4);
                    }
                }
            };

            stageA(0); CP_COMMIT;
            ull p01a = 0, p01b = 0, p23a = 0, p23b = 0;
            for (int kc = 0; kc < nc; kc++) {
                if (kc + 1 < nc) { stageA(kc + 1); CP_COMMIT; CP_WAIT1; }
                else             { CP_WAIT0; }
                __syncthreads();
                const int b = kc & 1;
                const float* Ab = sm + (b ? SM_A0_1 : SM_A0_0);
                if (side == 0) {
                    if (do0 && kc < 8)
                        mac_quad(p01a, p01b, p23a, p23b, Ab,
                                 sm + (b ? SM_W0_1 : SM_W0_0), gnl, gm0);
                } else {
                    if (do1)
                        mac_quad(p01a, p01b, p23a, p23b, Ab,
                                 sm + (b ? SM_W1_1 : SM_W1_0), gnl, gm0);
                }
                __syncthreads();
            }
            // epilogue
            if (side == 0 ? do0 : do1) {
                ull v01 = f2add(p01a, p01b);
                ull v23 = f2add(p23a, p23b);
                float bsc = side ? bg1[gn] : bg0[gn];
                float vx = plo(v01), vy = phi(v01), vz = plo(v23), vw = phi(v23);
                if (side == 0) {
                    const float* pre = g_gx0 + ((size_t)t * H2 + gn) * BB + gm0;
                    float4 p = *(const float4*)pre;
                    vx += p.x; vy += p.y; vz += p.z; vw += p.w;
                }
                float4 g;
                g.x = sigf(vx + bsc); g.y = sigf(vy + bsc);
                g.z = sigf(vz + bsc); g.w = sigf(vw + bsc);
                if (gn < H) {
                    const float* hsrc = side ? g_h1T : h0c;
                    float4 hh = *(const float4*)(hsrc + gn * BB + gm0);
                    float4 r;
                    r.x = g.x * hh.x; r.y = g.y * hh.y;
                    r.z = g.z * hh.z; r.w = g.w * hh.w;
                    float* dst = side ? g_rh1 : g_rh0;
                    *(float4*)(dst + gn * BB + gm0) = r;
                } else {
                    float* dst = side ? g_u1 : g_u0;
                    *(float4*)(dst + (gn - H) * BB + gm0) = g;
                }
            }
        }
        gsync();

        // ============== PHASE B: candidates + state update ==============
        {
            auto stageB = [&](int kc) {
                const int b = kc & 1;
                if (do0 && kc < 8) {
                    float* A0 = sm + (b ? SM_A0_1 : SM_A0_0);
                    const float* as0 = g_rh0 + kc * 4096;
                    #pragma unroll
                    for (int u = 0; u < 4; u++)
                        cp16(A0 + (tid + u * NTHR) * 4, as0 + (tid + u * NTHR) * 4);
                    float* W0 = sm + (b ? SM_W0_1 : SM_W0_0);
                    {
                        int q = tid >> 3, nl2 = tid & 7;
                        cp16(W0 + tid * 4,
                             g_Tc0 + ((size_t)(kc * 32 + q) * H + c * 8 + nl2) * 4);
                    }
                }
                if (do1) {
                    float* A1 = sm + (b ? SM_A1_1 : SM_A1_0);
                    const float* as1 = (kc < 8) ? (h0c + kc * 4096)
                                                : (g_rh1 + (kc - 8) * 4096);
                    #pragma unroll
                    for (int u = 0; u < 4; u++)
                        cp16(A1 + (tid + u * NTHR) * 4, as1 + (tid + u * NTHR) * 4);
                    float* W1 = sm + (b ? SM_W1_1 : SM_W1_0);
                    {
                        int q = tid >> 3, nl2 = tid & 7;
                        cp16(W1 + tid * 4,
                             g_Tc1 + ((size_t)(kc * 32 + q) * H + c * 8 + nl2) * 4);
                    }
                }
            };

            stageB(0); CP_COMMIT;
            ull pa = 0, pb = 0;
            for (int kc = 0; kc < nc; kc++) {
                if (kc + 1 < nc) { stageB(kc + 1); CP_COMMIT; CP_WAIT1; }
                else             { CP_WAIT0; }
                __syncthreads();
                const int b = kc & 1;
                if (side == 0) {
                    if (do0 && kc < 8)
                        mac_pair(pa, pb, sm + (b ? SM_A0_1 : SM_A0_0),
                                 sm + (b ? SM_W0_1 : SM_W0_0), cnl, cm0);
                } else {
                    if (do1)
                        mac_pair(pa, pb, sm + (b ? SM_A1_1 : SM_A1_0),
                                 sm + (b ? SM_W1_1 : SM_W1_0), cnl, cm0);
                }
                __syncthreads();
            }
            if (side == 0 ? do0 : do1) {
                ull v = f2add(pa, pb);
                if (side == 0) {
                    float2 p = *(const float2*)(g_cx0 + ((size_t)t * H + cn) * BB + cm0);
                    float b0 = bc0[cn];
                    float c0 = tanhx(plo(v) + p.x + b0);
                    float c1 = tanhx(phi(v) + p.y + b0);
                    float2 uu = *(const float2*)(g_u0 + cn * BB + cm0);
                    float2 hh = *(const float2*)(h0c + cn * BB + cm0);
                    float2 hn;
                    hn.x = uu.x * hh.x + (1.f - uu.x) * c0;
                    hn.y = uu.y * hh.y + (1.f - uu.y) * c1;
                    *(float2*)(g_h0T[cur ^ 1] + cn * BB + cm0) = hn;
                } else {
                    float b1 = bc1[cn];
                    float c0 = tanhx(plo(v) + b1);
                    float c1 = tanhx(phi(v) + b1);
                    float2 uu = *(const float2*)(g_u1 + cn * BB + cm0);
                    float2 hh = *(const float2*)(g_h1T + cn * BB + cm0);
                    float2 hn;
                    hn.x = uu.x * hh.x + (1.f - uu.x) * c0;
                    hn.y = uu.y * hh.y + (1.f - uu.y) * c1;
                    *(float2*)(g_h1T + cn * BB + cm0) = hn;
                    *(float2*)(g_outT + ((size_t)(t - 1) * H + cn) * BB + cm0) = hn;
                }
            }
        }
        cur ^= 1;
        gsync();
    }
}

// ---------------- launch ------------------------------------------------------
extern "C" void kernel_launch(void* const* d_in, const int* in_sizes, int n_in,
                              void* d_out, int out_size)
{
    const int*   idx = (const int*)  d_in[0];
    const float* emb = (const float*)d_in[1];
    const float* Wg0 = (const float*)d_in[2];
    const float* bg0 = (const float*)d_in[3];
    const float* Wc0 = (const float*)d_in[4];
    const float* bc0 = (const float*)d_in[5];
    const float* Wg1 = (const float*)d_in[6];
    const float* bg1 = (const float*)d_in[7];
    const float* Wc1 = (const float*)d_in[8];
    const float* bc1 = (const float*)d_in[9];
    const float* smb = (const float*)d_in[10];
    float* out = (float*)d_out;

    float *px, *pgx0, *pcx0, *poutT, *pout2, *pTg0, *pTc0, *pTg1, *pTc1;
    cudaGetSymbolAddress((void**)&px,    g_x);
    cudaGetSymbolAddress((void**)&pgx0,  g_gx0);
    cudaGetSymbolAddress((void**)&pcx0,  g_cx0);
    cudaGetSymbolAddress((void**)&poutT, g_outT);
    cudaGetSymbolAddress((void**)&pout2, g_out2);
    cudaGetSymbolAddress((void**)&pTg0,  g_Tg0);
    cudaGetSymbolAddress((void**)&pTc0,  g_Tc0);
    cudaGetSymbolAddress((void**)&pTg1,  g_Tg1);
    cudaGetSymbolAddress((void**)&pTc1,  g_Tc1);

    static bool attr_set = false;
    if (!attr_set) {
        cudaFuncSetAttribute(rnn_persist,
                             cudaFuncAttributeMaxDynamicSharedMemorySize,
                             SM_FLOATS * 4);
        attr_set = true;
    }

    // weight prep: transpose + k-quad interleave
    prep_w<<<(H * H2) / 256, 256>>>(Wg0, 1024, H2, H, H2, pTg0);
    prep_w<<<(H * H) / 256, 256>>>(Wc0, 1024, H, H, H, pTc0);
    prep_w<<<(H2 * H2) / 256, 256>>>(Wg1, 0, H2, H2, H2, pTg1);
    prep_w<<<(H2 * H) / 256, 256>>>(Wc1, 0, H, H2, H, pTc1);

    // embed
    embed_k<<<MROWS, 256>>>(idx, emb, px);

    // precompute layer-0 x-projections into [t][n][m] layout
    gemm_big<false, true><<<dim3(H2 / 64, MROWS / 128), 256>>>(px, Wg0, nullptr, pgx0,
                                                               MROWS, H2, H, H2);
    gemm_big<false, true><<<dim3(H / 64, MROWS / 128), 256>>>(px, Wc0, nullptr, pcx0,
                                                              MROWS, H, H, H);

    // pipelined recurrence (2 grid barriers per step)
    rnn_persist<<<NB, NTHR, SM_FLOATS * 4>>>(bg0, bc0, bg1, bc1);

    // reorder h1 sequence to [m*T+t][n]
    transp_out<<<dim3(TT, H / 32), dim3(32, 8)>>>(poutT, pout2);

    // tied-softmax logits
    gemm_big<true, false><<<dim3((VOCAB + 63) / 64, MROWS / 128), 256>>>(pout2, emb, smb,
                                                                         out, MROWS, VOCAB,
                                                                         H, H);
}

// round 4
// speedup vs baseline: 1.5190x; 1.0539x over previous
#include <cuda_runtime.h>
#include <math.h>

typedef unsigned long long ull;

#define VOCAB 10000
#define H 1024
#define H2 2048
#define BB 32
#define TT 128
#define MROWS (BB*TT)   // 4096
#define NB 128          // persistent grid CTAs
#define NTHR 256

// smem layout (floats), dynamic: total 24576 floats = 96KB
#define SM_A0_0 0
#define SM_A0_1 4096
#define SM_A1_0 8192
#define SM_A1_1 12288
#define SM_W0_0 16384
#define SM_W0_1 18432
#define SM_W1_0 20480
#define SM_W1_1 22528
#define SM_FLOATS 24576

// ---------------- scratch (device globals; no allocations allowed) ----------
__device__ __align__(16) float g_x[MROWS * H];
__device__ __align__(16) float g_gx0[TT * H2 * BB];     // [t][n][m]
__device__ __align__(16) float g_cx0[TT * H * BB];      // [t][n][m]
__device__ __align__(16) float g_outT[TT * H * BB];     // [t][n][m]
__device__ __align__(16) float g_out2[MROWS * H];       // [m*T+t][n]
__device__ __align__(16) float g_h0T[2][H * BB];        // ping-pong
__device__ __align__(16) float g_h1T[H * BB];
__device__ __align__(16) float g_rh0[H * BB];
__device__ __align__(16) float g_u0[H * BB];
__device__ __align__(16) float g_rh1[H * BB];
__device__ __align__(16) float g_u1[H * BB];
__device__ __align__(16) float g_Tg0[H * H2];           // [(k/4)*N + n][4]
__device__ __align__(16) float g_Tc0[H * H];
__device__ __align__(16) float g_Tg1[H2 * H2];
__device__ __align__(16) float g_Tc1[H2 * H];
__device__ volatile unsigned g_cnt;
__device__ volatile unsigned g_gen;

// ---------------- f32x2 packed helpers --------------------------------------
__device__ __forceinline__ ull pdup(float x) {
    ull r; asm("mov.b64 %0, {%1, %1};" : "=l"(r) : "f"(x)); return r;
}
__device__ __forceinline__ ull f2fma(ull acc, ull a, ull b) {
    ull d; asm("fma.rn.f32x2 %0, %1, %2, %3;" : "=l"(d) : "l"(a), "l"(b), "l"(acc));
    return d;
}
__device__ __forceinline__ ull f2add(ull a, ull b) {
    ull d; asm("add.rn.f32x2 %0, %1, %2;" : "=l"(d) : "l"(a), "l"(b)); return d;
}
__device__ __forceinline__ float plo(ull v) { return __uint_as_float((unsigned)v); }
__device__ __forceinline__ float phi(ull v) { return __uint_as_float((unsigned)(v >> 32)); }

__device__ __forceinline__ float sigf(float x) {
    return __fdividef(1.f, 1.f + __expf(-x));
}
__device__ __forceinline__ float tanhx(float x) {
    return 1.f - __fdividef(2.f, __expf(2.f * x) + 1.f);
}

// ---------------- cp.async ----------------------------------------------------
__device__ __forceinline__ void cp16(float* d, const float* s) {
    unsigned ds = (unsigned)__cvta_generic_to_shared(d);
    asm volatile("cp.async.cg.shared.global [%0], [%1], 16;" :: "r"(ds), "l"(s) : "memory");
}
#define CP_COMMIT asm volatile("cp.async.commit_group;" ::: "memory")
#define CP_WAIT1  asm volatile("cp.async.wait_group 1;" ::: "memory")
#define CP_WAIT0  asm volatile("cp.async.wait_group 0;" ::: "memory")

// ---------------- grid barrier ------------------------------------------------
__device__ __forceinline__ void gsync() {
    __threadfence();
    __syncthreads();
    if (threadIdx.x == 0) {
        unsigned gen = g_gen;
        unsigned old = atomicAdd((unsigned*)&g_cnt, 1u);
        if (old == NB - 1) {
            g_cnt = 0;
            __threadfence();
            g_gen = gen + 1;
        } else {
            while (g_gen == gen) { }
        }
    }
    __syncthreads();
}

// ---------------- small utility kernels --------------------------------------
__global__ void embed_k(const int* __restrict__ idx, const float* __restrict__ emb,
                        float* __restrict__ x) {
    int row = blockIdx.x;
    int tid = threadIdx.x;
    const float4* src = (const float4*)(emb + (size_t)idx[row] * H);
    float4* dst = (float4*)(x + (size_t)row * H);
    dst[tid] = src[tid];
}

__global__ void prep_w(const float* __restrict__ src, int srow0, int ld,
                       int K, int N, float* __restrict__ dst) {
    int idx = blockIdx.x * 256 + threadIdx.x;
    if (idx >= K * N) return;
    int k = idx / N;
    int n = idx - k * N;
    dst[((size_t)(k >> 2) * N + n) * 4 + (k & 3)] = src[(size_t)(srow0 + k) * ld + n];
}

__global__ void transp_out(const float* __restrict__ outT, float* __restrict__ out) {
    __shared__ float s[32][33];
    int t = blockIdx.x;
    int nb = blockIdx.y * 32;
    int tx = threadIdx.x, ty = threadIdx.y;
#pragma unroll
    for (int i = 0; i < 32; i += 8)
        s[ty + i][tx] = outT[((size_t)t * H + nb + ty + i) * BB + tx];
    __syncthreads();
#pragma unroll
    for (int i = 0; i < 32; i += 8)
        out[((size_t)(ty + i) * TT + t) * H + nb + tx] = s[tx][ty + i];
}

// ---------------- big GEMM (f32x2) -------------------------------------------
template<bool BT, bool GRUL>
__global__ void gemm_big(const float* __restrict__ A, const float* __restrict__ Bm,
                         const float* __restrict__ bias, float* __restrict__ C,
                         int M, int N, int K, int ldb)
{
    __shared__ __align__(16) float As[16][132];
    __shared__ __align__(16) float Bs[16][68];

    int m0 = blockIdx.y * 128;
    int n0 = blockIdx.x * 64;
    int tid = threadIdx.x;
    int rowg = tid >> 4;
    int colg = tid & 15;
    int mm0 = rowg * 8;
    int nn0 = colg * 4;

    ull acc2[4][4];
#pragma unroll
    for (int p = 0; p < 4; p++)
#pragma unroll
        for (int c = 0; c < 4; c++) acc2[p][c] = 0ull;

    for (int k0 = 0; k0 < K; k0 += 16) {
#pragma unroll
        for (int i = 0; i < 2; i++) {
            int f  = tid + i * 256;
            int am = f >> 2;
            int kq = f & 3;
            float4 v = *(const float4*)(A + (size_t)(m0 + am) * K + k0 + kq * 4);
            As[kq * 4 + 0][am] = v.x;
            As[kq * 4 + 1][am] = v.y;
            As[kq * 4 + 2][am] = v.z;
            As[kq * 4 + 3][am] = v.w;
        }
        if (!BT) {
            int brow = tid >> 4;
            int colq = tid & 15;
            int n = n0 + colq * 4;
            float4 v;
            if (n + 3 < N) {
                v = *(const float4*)(Bm + (size_t)(k0 + brow) * ldb + n);
            } else {
                v.x = (n + 0 < N) ? Bm[(size_t)(k0 + brow) * ldb + n + 0] : 0.f;
                v.y = (n + 1 < N) ? Bm[(size_t)(k0 + brow) * ldb + n + 1] : 0.f;
                v.z = (n + 2 < N) ? Bm[(size_t)(k0 + brow) * ldb + n + 2] : 0.f;
                v.w = (n + 3 < N) ? Bm[(size_t)(k0 + brow) * ldb + n + 3] : 0.f;
            }
            *(float4*)&Bs[brow][colq * 4] = v;
        } else {
            int nrow = tid >> 2;
            int kq = tid & 3;
            int n = n0 + nrow;
            float4 v = make_float4(0.f, 0.f, 0.f, 0.f);
            if (n < N) v = *(const float4*)(Bm + (size_t)n * ldb + k0 + kq * 4);
            Bs[kq * 4 + 0][nrow] = v.x;
            Bs[kq * 4 + 1][nrow] = v.y;
            Bs[kq * 4 + 2][nrow] = v.z;
            Bs[kq * 4 + 3][nrow] = v.w;
        }
        __syncthreads();
#pragma unroll
        for (int kk = 0; kk < 16; kk++) {
            ulonglong2 a01 = *(const ulonglong2*)&As[kk][mm0];
            ulonglong2 a23 = *(const ulonglong2*)&As[kk][mm0 + 4];
            float4 tb = *(const float4*)&Bs[kk][nn0];
            ull b0 = pdup(tb.x), b1 = pdup(tb.y), b2 = pdup(tb.z), b3 = pdup(tb.w);
            acc2[0][0] = f2fma(acc2[0][0], a01.x, b0);
            acc2[0][1] = f2fma(acc2[0][1], a01.x, b1);
            acc2[0][2] = f2fma(acc2[0][2], a01.x, b2);
            acc2[0][3] = f2fma(acc2[0][3], a01.x, b3);
            acc2[1][0] = f2fma(acc2[1][0], a01.y, b0);
            acc2[1][1] = f2fma(acc2[1][1], a01.y, b1);
            acc2[1][2] = f2fma(acc2[1][2], a01.y, b2);
            acc2[1][3] = f2fma(acc2[1][3], a01.y, b3);
            acc2[2][0] = f2fma(acc2[2][0], a23.x, b0);
            acc2[2][1] = f2fma(acc2[2][1], a23.x, b1);
            acc2[2][2] = f2fma(acc2[2][2], a23.x, b2);
            acc2[2][3] = f2fma(acc2[2][3], a23.x, b3);
            acc2[3][0] = f2fma(acc2[3][0], a23.y, b0);
            acc2[3][1] = f2fma(acc2[3][1], a23.y, b1);
            acc2[3][2] = f2fma(acc2[3][2], a23.y, b2);
            acc2[3][3] = f2fma(acc2[3][3], a23.y, b3);
        }
        __syncthreads();
    }

#pragma unroll
    for (int p = 0; p < 4; p++) {
#pragma unroll
        for (int c = 0; c < 4; c++) {
            int n = n0 + nn0 + c;
            if (n < N) {
                float v0 = plo(acc2[p][c]);
                float v1 = phi(acc2[p][c]);
                if (bias) { v0 += bias[n]; v1 += bias[n]; }
                int r0 = m0 + mm0 + 2 * p;
                int r1 = r0 + 1;
                if (GRUL) {
                    C[((size_t)(r0 & (TT - 1)) * N + n) * BB + (r0 >> 7)] = v0;
                    C[((size_t)(r1 & (TT - 1)) * N + n) * BB + (r1 >> 7)] = v1;
                } else {
                    C[(size_t)r0 * N + n] = v0;
                    C[(size_t)r1 * N + n] = v1;
                }
            }
        }
    }
}

// ---------------- recurrence MAC cores ----------------------------------------
// gates: one n-column, 4 batch rows (m0..m0+3), per q: 1 LDS.128 W + 4 LDS.128 A
// + 8 f2fma. Wb slice has 16 n columns.
__device__ __forceinline__ void mac_quad(ull& p01a, ull& p01b, ull& p23a, ull& p23b,
                                         const float* __restrict__ Ab,
                                         const float* __restrict__ Wb,
                                         int nl, int m0)
{
    const float4* wp = (const float4*)Wb + nl;
#pragma unroll 8
    for (int q = 0; q < 32; q++) {
        float4 w = wp[q * 16];
        const float* ak = Ab + q * 128 + m0;
        ulonglong2 a0 = *(const ulonglong2*)(ak);
        ulonglong2 a1 = *(const ulonglong2*)(ak + 32);
        ulonglong2 a2 = *(const ulonglong2*)(ak + 64);
        ulonglong2 a3 = *(const ulonglong2*)(ak + 96);
        ull w0 = pdup(w.x), w1 = pdup(w.y), w2 = pdup(w.z), w3 = pdup(w.w);
        p01a = f2fma(p01a, a0.x, w0); p23a = f2fma(p23a, a0.y, w0);
        p01b = f2fma(p01b, a1.x, w1); p23b = f2fma(p23b, a1.y, w1);
        p01a = f2fma(p01a, a2.x, w2); p23a = f2fma(p23a, a2.y, w2);
        p01b = f2fma(p01b, a3.x, w3); p23b = f2fma(p23b, a3.y, w3);
    }
}

// cand: one n-column, 2 batch rows. Wb slice has 8 n columns.
__device__ __forceinline__ void mac_pair(ull& pa, ull& pb,
                                         const float* __restrict__ Ab,
                                         const float* __restrict__ Wb,
                                         int nl, int m0)
{
    const float4* wp = (const float4*)Wb + nl;
#pragma unroll 8
    for (int q = 0; q < 32; q++) {
        float4 w = wp[q * 8];
        const float* ak = Ab + q * 128 + m0;
        ull a0 = *(const ull*)(ak);
        ull a1 = *(const ull*)(ak + 32);
        ull a2 = *(const ull*)(ak + 64);
        ull a3 = *(const ull*)(ak + 96);
        pa = f2fma(pa, a0, pdup(w.x));
        pb = f2fma(pb, a1, pdup(w.y));
        pa = f2fma(pa, a2, pdup(w.z));
        pb = f2fma(pb, a3, pdup(w.w));
    }
}

// ---------------- persistent pipelined recurrence -----------------------------
__global__ void __launch_bounds__(NTHR, 1)
rnn_persist(const float* __restrict__ bg0, const float* __restrict__ bc0,
            const float* __restrict__ bg1, const float* __restrict__ bc1)
{
    extern __shared__ __align__(16) float sm[];
    const int tid = threadIdx.x;
    const int c   = blockIdx.x;
    const int gt  = c * NTHR + tid;

    // zero initial states
    g_h0T[0][gt] = 0.f;
    g_h1T[gt] = 0.f;
    g_h0T[0][gt + NB * NTHR] = 0.f;     // cover full 32768? H*BB = 32768 = NB*NTHR
    // (H*BB == NB*NTHR == 32768, so first two lines cover everything; third is a
    //  duplicate guard only if sizes changed — remove effect by clamping)
    gsync();

    const int side = tid >> 7;          // 0: layer0 work, 1: layer1 work
    const int idx  = tid & 127;
    // gates mapping
    const int gnl = idx >> 3, gm0 = (idx & 7) * 4;
    const int gn  = c * 16 + gnl;
    // cand mapping
    const int cnl = idx >> 4, cm0 = (idx & 15) * 2;
    const int cn  = c * 8 + cnl;

    int cur = 0;

    for (int t = 0; t <= TT; t++) {
        const bool do0 = (t < TT);
        const bool do1 = (t > 0);
        const float* __restrict__ h0c = g_h0T[cur];
        const int nc = do1 ? 16 : 8;

        // ============== PHASE A: gates ==============
        {
            // ---- stage chunk kc into buffer b
            auto stageA = [&](int kc) {
                float* A0 = sm + ((kc & 1) ? SM_A0_1 : SM_A0_0);
                const float* hs = (kc < 8) ? (h0c + kc * 4096)
                                           : (g_h1T + (kc - 8) * 4096);
                #pragma unroll
                for (int u = 0; u < 4; u++)
                    cp16(A0 + (tid + u * NTHR) * 4, hs + (tid + u * NTHR) * 4);
                if (do0 && kc < 8) {
                    float* W0 = sm + ((kc & 1) ? SM_W0_1 : SM_W0_0);
                    #pragma unroll
                    for (int u = 0; u < 2; u++) {
                        int e = tid + u * NTHR;
                        int q = e >> 4, nl2 = e & 15;
                        cp16(W0 + e * 4,
                             g_Tg0 + ((size_t)(kc * 32 + q) * H2 + c * 16 + nl2) * 4);
                    }
                }
                if (do1) {
                    float* W1 = sm + ((kc & 1) ? SM_W1_1 : SM_W1_0);
                    #pragma unroll
                    for (int u = 0; u < 2; u++) {
                        int e = tid + u * NTHR;
                        int q = e >> 4, nl2 = e & 15;
                        cp16(W1 + e * 4,
                             g_Tg1 + ((size_t)(kc * 32 + q) * H2 + c * 16 + nl2) * 4);
                    }
                }
            };

            stageA(0); CP_COMMIT;
            ull p01a = 0, p01b = 0, p23a = 0, p23b = 0;
            for (int kc = 0; kc < nc; kc++) {
                if (kc + 1 < nc) { stageA(kc + 1); CP_COMMIT; CP_WAIT1; }
                else             { CP_WAIT0; }
                __syncthreads();
                const int b = kc & 1;
                const float* Ab = sm + (b ? SM_A0_1 : SM_A0_0);
                if (side == 0) {
                    if (do0 && kc < 8)
                        mac_quad(p01a, p01b, p23a, p23b, Ab,
                                 sm + (b ? SM_W0_1 : SM_W0_0), gnl, gm0);
                } else {
                    if (do1)
                        mac_quad(p01a, p01b, p23a, p23b, Ab,
                                 sm + (b ? SM_W1_1 : SM_W1_0), gnl, gm0);
                }
                __syncthreads();
            }
            // epilogue
            if (side == 0 ? do0 : do1) {
                ull v01 = f2add(p01a, p01b);
                ull v23 = f2add(p23a, p23b);
                float bsc = side ? bg1[gn] : bg0[gn];
                float vx = plo(v01), vy = phi(v01), vz = plo(v23), vw = phi(v23);
                if (side == 0) {
                    const float* pre = g_gx0 + ((size_t)t * H2 + gn) * BB + gm0;
                    float4 p = *(const float4*)pre;
                    vx += p.x; vy += p.y; vz += p.z; vw += p.w;
                }
                float4 g;
                g.x = sigf(vx + bsc); g.y = sigf(vy + bsc);
                g.z = sigf(vz + bsc); g.w = sigf(vw + bsc);
                if (gn < H) {
                    const float* hsrc = side ? g_h1T : h0c;
                    float4 hh = *(const float4*)(hsrc + gn * BB + gm0);
                    float4 r;
                    r.x = g.x * hh.x; r.y = g.y * hh.y;
                    r.z = g.z * hh.z; r.w = g.w * hh.w;
                    float* dst = side ? g_rh1 : g_rh0;
                    *(float4*)(dst + gn * BB + gm0) = r;
                } else {
                    float* dst = side ? g_u1 : g_u0;
                    *(float4*)(dst + (gn - H) * BB + gm0) = g;
                }
            }
        }
        gsync();

        // ============== PHASE B: candidates + state update ==============
        {
            auto stageB = [&](int kc) {
                const int b = kc & 1;
                if (do0 && kc < 8) {
                    float* A0 = sm + (b ? SM_A0_1 : SM_A0_0);
                    const float* as0 = g_rh0 + kc * 4096;
                    #pragma unroll
                    for (int u = 0; u < 4; u++)
                        cp16(A0 + (tid + u * NTHR) * 4, as0 + (tid + u * NTHR) * 4);
                    float* W0 = sm + (b ? SM_W0_1 : SM_W0_0);
                    {
                        int q = tid >> 3, nl2 = tid & 7;
                        cp16(W0 + tid * 4,
                             g_Tc0 + ((size_t)(kc * 32 + q) * H + c * 8 + nl2) * 4);
                    }
                }
                if (do1) {
                    float* A1 = sm + (b ? SM_A1_1 : SM_A1_0);
                    const float* as1 = (kc < 8) ? (h0c + kc * 4096)
                                                : (g_rh1 + (kc - 8) * 4096);
                    #pragma unroll
                    for (int u = 0; u < 4; u++)
                        cp16(A1 + (tid + u * NTHR) * 4, as1 + (tid + u * NTHR) * 4);
                    float* W1 = sm + (b ? SM_W1_1 : SM_W1_0);
                    {
                        int q = tid >> 3, nl2 = tid & 7;
                        cp16(W1 + tid * 4,
                             g_Tc1 + ((size_t)(kc * 32 + q) * H + c * 8 + nl2) * 4);
                    }
                }
            };

            stageB(0); CP_COMMIT;
            ull pa = 0, pb = 0;
            for (int kc = 0; kc < nc; kc++) {
                if (kc + 1 < nc) { stageB(kc + 1); CP_COMMIT; CP_WAIT1; }
                else             { CP_WAIT0; }
                __syncthreads();
                const int b = kc & 1;
                if (side == 0) {
                    if (do0 && kc < 8)
                        mac_pair(pa, pb, sm + (b ? SM_A0_1 : SM_A0_0),
                                 sm + (b ? SM_W0_1 : SM_W0_0), cnl, cm0);
                } else {
                    if (do1)
                        mac_pair(pa, pb, sm + (b ? SM_A1_1 : SM_A1_0),
                                 sm + (b ? SM_W1_1 : SM_W1_0), cnl, cm0);
                }
                __syncthreads();
            }
            if (side == 0 ? do0 : do1) {
                ull v = f2add(pa, pb);
                if (side == 0) {
                    float2 p = *(const float2*)(g_cx0 + ((size_t)t * H + cn) * BB + cm0);
                    float b0 = bc0[cn];
                    float c0 = tanhx(plo(v) + p.x + b0);
                    float c1 = tanhx(phi(v) + p.y + b0);
                    float2 uu = *(const float2*)(g_u0 + cn * BB + cm0);
                    float2 hh = *(const float2*)(h0c + cn * BB + cm0);
                    float2 hn;
                    hn.x = uu.x * hh.x + (1.f - uu.x) * c0;
                    hn.y = uu.y * hh.y + (1.f - uu.y) * c1;
                    *(float2*)(g_h0T[cur ^ 1] + cn * BB + cm0) = hn;
                } else {
                    float b1 = bc1[cn];
                    float c0 = tanhx(plo(v) + b1);
                    float c1 = tanhx(phi(v) + b1);
                    float2 uu = *(const float2*)(g_u1 + cn * BB + cm0);
                    float2 hh = *(const float2*)(g_h1T + cn * BB + cm0);
                    float2 hn;
                    hn.x = uu.x * hh.x + (1.f - uu.x) * c0;
                    hn.y = uu.y * hh.y + (1.f - uu.y) * c1;
                    *(float2*)(g_h1T + cn * BB + cm0) = hn;
                    *(float2*)(g_outT + ((size_t)(t - 1) * H + cn) * BB + cm0) = hn;
                }
            }
        }
        cur ^= 1;
        gsync();
    }
}

// ---------------- launch ------------------------------------------------------
extern "C" void kernel_launch(void* const* d_in, const int* in_sizes, int n_in,
                              void* d_out, int out_size)
{
    const int*   idx = (const int*)  d_in[0];
    const float* emb = (const float*)d_in[1];
    const float* Wg0 = (const float*)d_in[2];
    const float* bg0 = (const float*)d_in[3];
    const float* Wc0 = (const float*)d_in[4];
    const float* bc0 = (const float*)d_in[5];
    const float* Wg1 = (const float*)d_in[6];
    const float* bg1 = (const float*)d_in[7];
    const float* Wc1 = (const float*)d_in[8];
    const float* bc1 = (const float*)d_in[9];
    const float* smb = (const float*)d_in[10];
    float* out = (float*)d_out;

    float *px, *pgx0, *pcx0, *poutT, *pout2, *pTg0, *pTc0, *pTg1, *pTc1;
    cudaGetSymbolAddress((void**)&px,    g_x);
    cudaGetSymbolAddress((void**)&pgx0,  g_gx0);
    cudaGetSymbolAddress((void**)&pcx0,  g_cx0);
    cudaGetSymbolAddress((void**)&poutT, g_outT);
    cudaGetSymbolAddress((void**)&pout2, g_out2);
    cudaGetSymbolAddress((void**)&pTg0,  g_Tg0);
    cudaGetSymbolAddress((void**)&pTc0,  g_Tc0);
    cudaGetSymbolAddress((void**)&pTg1,  g_Tg1);
    cudaGetSymbolAddress((void**)&pTc1,  g_Tc1);

    static bool attr_set = false;
    if (!attr_set) {
        cudaFuncSetAttribute(rnn_persist,
                             cudaFuncAttributeMaxDynamicSharedMemorySize,
                             SM_FLOATS * 4);
        attr_set = true;
    }

    // weight prep: transpose + k-quad interleave
    prep_w<<<(H * H2) / 256, 256>>>(Wg0, 1024, H2, H, H2, pTg0);
    prep_w<<<(H * H) / 256, 256>>>(Wc0, 1024, H, H, H, pTc0);
    prep_w<<<(H2 * H2) / 256, 256>>>(Wg1, 0, H2, H2, H2, pTg1);
    prep_w<<<(H2 * H) / 256, 256>>>(Wc1, 0, H, H2, H, pTc1);

    // embed
    embed_k<<<MROWS, 256>>>(idx, emb, px);

    // precompute layer-0 x-projections into [t][n][m] layout
    gemm_big<false, true><<<dim3(H2 / 64, MROWS / 128), 256>>>(px, Wg0, nullptr, pgx0,
                                                               MROWS, H2, H, H2);
    gemm_big<false, true><<<dim3(H / 64, MROWS / 128), 256>>>(px, Wc0, nullptr, pcx0,
                                                              MROWS, H, H, H);

    // pipelined recurrence (2 grid barriers per step)
    rnn_persist<<<NB, NTHR, SM_FLOATS * 4>>>(bg0, bc0, bg1, bc1);

    // reorder h1 sequence to [m*T+t][n]
    transp_out<<<dim3(TT, H / 32), dim3(32, 8)>>>(poutT, pout2);

    // tied-softmax logits
    gemm_big<true, false><<<dim3((VOCAB + 63) / 64, MROWS / 128), 256>>>(pout2, emb, smb,
                                                                         out, MROWS, VOCAB,
                                                                         H, H);
}